// round 11
// baseline (speedup 1.0000x reference)
#include <cuda_runtime.h>

// EPS_68771016344265: 2x2 tensor-network contraction, S=2, OUT=4
// out[b,h,w,o] = sum_{s0..s3} x_h[w][s0] x_h[w+1][s1] x_{h+1}[w][s2] x_{h+1}[w+1][s3]
//               * core[s0,s1,s2,s3,o]
// q(h) = x_h[w] (x) x_h[w+1];  d(h)_j = sum_i q(h)_i C[i][j][:];  out(h) = sum_j q(h+1)_j d(h)_j
//
// o-dim split across thread pairs (even lane -> o{0,1}, odd -> o{2,3}); per-thread half-core
// = 16 f32x2 = 32 regs, register resident. NEW in R11: explicit P=4 rotating load buffer --
// row k's input is issued 3 unrolled iterations before use, converting the per-row
// ~250-400cyc scoreboard stall into overlapped prefetch.

#define NB 128
#define NH 128
#define NW 128
#define HN 127
#define WN 127
#define TH 16
#define PF 4            // prefetch ring depth (load->use distance = PF-1 rows)

typedef unsigned long long u64;

__device__ __forceinline__ u64 f2mul(u64 a, u64 b) {
    u64 r; asm("mul.rn.f32x2 %0,%1,%2;" : "=l"(r) : "l"(a), "l"(b)); return r;
}
__device__ __forceinline__ u64 f2fma(u64 a, u64 b, u64 c) {
    u64 r; asm("fma.rn.f32x2 %0,%1,%2,%3;" : "=l"(r) : "l"(a), "l"(b), "l"(c)); return r;
}
__device__ __forceinline__ u64 fdup(float x) {
    u64 r; asm("mov.b64 %0,{%1,%1};" : "=l"(r) : "f"(x)); return r;
}
__device__ __forceinline__ float2 f2unpack(u64 a) {
    float2 v; asm("mov.b64 {%0,%1},%2;" : "=f"(v.x), "=f"(v.y) : "l"(a)); return v;
}

template <int NROWS>   // pixel rows in this strip; input rows = NROWS+1 (compile-time)
__device__ __forceinline__ void run_strip(const float2* __restrict__ ip,   // strip row 0, float2 units
                                          const u64* __restrict__ c,
                                          float2* __restrict__ outp,      // pixel (h0,w), o-pair slot
                                          int w, int wp1, bool st)
{
    float2 A[PF], B[PF];             // rotating prefetch ring (indices compile-time under unroll)

    // Preload input rows 0..PF-1 (all offsets immediate)
    #pragma unroll
    for (int k = 0; k < PF && k <= NROWS; ++k) {
        A[k] = ip[k * NW + w];
        B[k] = ip[k * NW + wp1];
    }

    // Row 0: q and initial d
    u64 q0 = fdup(A[0].x * B[0].x);
    u64 q1 = fdup(A[0].x * B[0].y);
    u64 q2 = fdup(A[0].y * B[0].x);
    u64 q3 = fdup(A[0].y * B[0].y);

    u64 d[4];
    #pragma unroll
    for (int j = 0; j < 4; j++)
        d[j] = f2fma(q3, c[12+j], f2fma(q2, c[8+j], f2fma(q1, c[4+j], f2mul(q0, c[j]))));

    #pragma unroll
    for (int k = 1; k <= NROWS; ++k) {
        // Prefetch row k+PF-1 into the slot being vacated this iteration
        if (k + PF - 1 <= NROWS) {
            A[(k + PF - 1) % PF] = ip[(k + PF - 1) * NW + w];
            B[(k + PF - 1) % PF] = ip[(k + PF - 1) * NW + wp1];
        }

        float2 ya = A[k % PF];
        float2 yb = B[k % PF];
        u64 p0 = fdup(ya.x * yb.x);
        u64 p1 = fdup(ya.x * yb.y);
        u64 p2 = fdup(ya.y * yb.x);
        u64 p3 = fdup(ya.y * yb.y);

        // pixel row k-1: this thread's o-pair = sum_j p_j * d_j
        u64 o2 = f2fma(p3, d[3], f2fma(p2, d[2], f2fma(p1, d[1], f2mul(p0, d[0]))));
        if (st) outp[(k - 1) * 2 * WN] = f2unpack(o2);

        if (k < NROWS) {             // d for next pixel (dead on last row)
            #pragma unroll
            for (int j = 0; j < 4; j++)
                d[j] = f2fma(p3, c[12+j], f2fma(p2, c[8+j], f2fma(p1, c[4+j], f2mul(p0, c[j]))));
        }
    }
}

__global__ __launch_bounds__(128, 6)
void eps_kernel(const float* __restrict__ in,
                const float* __restrict__ core,
                float2* __restrict__ out)
{
    const int lane = threadIdx.x;
    const int slot = lane >> 1;
    const int op   = lane & 1;                       // which o-pair this thread owns
    const int w    = blockIdx.y * 64 + slot;         // 0..127
    const int b    = blockIdx.z;
    const int h0   = blockIdx.x * TH;

    const float2* ip = reinterpret_cast<const float2*>(in) + (b * NH + h0) * NW;
    const int wp1 = (w < NW - 1) ? (w + 1) : w;      // clamp; w=127 never stores
    float2* outp = out + ((long)(b * HN + h0) * WN + w) * 2 + op;
    const bool st = (w < WN);

    // Per-thread half-core: c[k] = {core[k][2*op], core[k][2*op+1]}
    u64 c[16];
    {
        const u64* cp = reinterpret_cast<const u64*>(core);
        #pragma unroll
        for (int k = 0; k < 16; k++) c[k] = cp[2 * k + op];
    }

    if (h0 + TH < HN) {
        run_strip<TH>(ip, c, outp, w, wp1, st);               // strips 0..6: 16 rows
    } else {
        run_strip<HN - 7 * TH>(ip, c, outp, w, wp1, st);      // strip 7: 15 rows
    }
}

extern "C" void kernel_launch(void* const* d_in, const int* in_sizes, int n_in,
                              void* d_out, int out_size)
{
    const float* in   = (const float*)d_in[0];   // (1,128,128,128,2) f32
    const float* core = (const float*)d_in[1];   // (2,2,2,2,4) f32
    float2* out = (float2*)d_out;                // (128,127,127,4) f32 viewed as float2

    dim3 grid((HN + TH - 1) / TH, 2, NB);        // (8, 2, 128) = 2048 blocks
    eps_kernel<<<grid, 128>>>(in, core, out);
}